// round 3
// baseline (speedup 1.0000x reference)
#include <cuda_runtime.h>

#define B_ 2
#define T_ 2048
#define D_ 1024
#define H_ 16
#define HD_ 64
#define NTOK (B_*T_)      // 4096
#define D3 (3*D_)         // 3072

// Scratch (static device arrays: allocation-free)
__device__ float g_q[B_*H_*T_*HD_];   // [B,H,T,HD]
__device__ float g_k[B_*H_*T_*HD_];
__device__ float g_v[B_*H_*T_*HD_];
__device__ float g_y[B_*T_*D_];       // attention output [B,T,D]

// ---------------------------------------------------------------------------
// SGEMM: C[M,N] = A[M,K] @ B[K,N] + bias[N]
// mode 1: A = x, epilogue scatters into g_q/g_k/g_v ([B,H,T,HD] layout)
// mode 2: A = g_y (ignore A arg), plain row-major write to C
// ---------------------------------------------------------------------------
#define BM 128
#define BN 128
#define BKK 8

__global__ __launch_bounds__(256)
void sgemm_kernel(const float* __restrict__ A, const float* __restrict__ Bm,
                  const float* __restrict__ bias, float* __restrict__ C,
                  int M, int N, int K, int mode)
{
    __shared__ float As[BKK][BM];
    __shared__ float Bs[BKK][BN];

    const int tid = threadIdx.x;
    const int tx = tid & 15;          // 0..15 -> col quad
    const int ty = tid >> 4;          // 0..15 -> row quad
    const int m0 = blockIdx.y * BM;
    const int n0 = blockIdx.x * BN;

    const float* __restrict__ Ap = (mode == 2) ? g_y : A;

    const int aRow = tid >> 1;            // 0..127
    const int aK4  = (tid & 1) * 4;       // 0 or 4
    const int bRow = tid >> 5;            // 0..7
    const int bC4  = (tid & 31) * 4;      // 0..124

    float acc[8][8];
#pragma unroll
    for (int i = 0; i < 8; i++)
#pragma unroll
        for (int j = 0; j < 8; j++) acc[i][j] = 0.f;

    for (int kt = 0; kt < K; kt += BKK) {
        float4 va = *(const float4*)&Ap[(size_t)(m0 + aRow) * K + kt + aK4];
        float4 vb = *(const float4*)&Bm[(size_t)(kt + bRow) * N + n0 + bC4];

        __syncthreads();   // previous tile compute done
        As[aK4 + 0][aRow] = va.x;
        As[aK4 + 1][aRow] = va.y;
        As[aK4 + 2][aRow] = va.z;
        As[aK4 + 3][aRow] = va.w;
        *(float4*)&Bs[bRow][bC4] = vb;
        __syncthreads();

#pragma unroll
        for (int k = 0; k < BKK; k++) {
            float4 a0 = *(const float4*)&As[k][ty * 4];
            float4 a1 = *(const float4*)&As[k][ty * 4 + 64];
            float4 b0 = *(const float4*)&Bs[k][tx * 4];
            float4 b1 = *(const float4*)&Bs[k][tx * 4 + 64];
            float ar[8] = {a0.x, a0.y, a0.z, a0.w, a1.x, a1.y, a1.z, a1.w};
            float br[8] = {b0.x, b0.y, b0.z, b0.w, b1.x, b1.y, b1.z, b1.w};
#pragma unroll
            for (int i = 0; i < 8; i++)
#pragma unroll
                for (int j = 0; j < 8; j++)
                    acc[i][j] = fmaf(ar[i], br[j], acc[i][j]);
        }
    }

    // epilogue
#pragma unroll
    for (int i = 0; i < 8; i++) {
        int r = m0 + ((i < 4) ? (ty * 4 + i) : (64 + ty * 4 + i - 4));
#pragma unroll
        for (int jh = 0; jh < 2; jh++) {
            int c = n0 + jh * 64 + tx * 4;
            float4 v;
            v.x = acc[i][jh * 4 + 0] + bias[c + 0];
            v.y = acc[i][jh * 4 + 1] + bias[c + 1];
            v.z = acc[i][jh * 4 + 2] + bias[c + 2];
            v.w = acc[i][jh * 4 + 3] + bias[c + 3];
            if (mode == 1) {
                // scatter qkv: col = which*1024 + h*64 + hd (quad stays in one head)
                int which = c >> 10;          // c / 1024
                int rem   = c & 1023;
                int h     = rem >> 6;
                int hd    = rem & 63;
                int b     = r / T_;
                int t     = r - b * T_;
                float* dst = (which == 0) ? g_q : (which == 1) ? g_k : g_v;
                *(float4*)&dst[(((size_t)b * H_ + h) * T_ + t) * HD_ + hd] = v;
            } else {
                *(float4*)&C[(size_t)r * N + c] = v;
            }
        }
    }
}

// ---------------------------------------------------------------------------
// Causal flash attention, fp32.
// Grid: (T/128, B*H). Block: 128 threads; thread t owns q-row q0+t.
// q row + O accumulator in registers; K/V staged in smem 64 keys at a time;
// all lanes read the same K/V float4 (broadcast) -> LDS:FMA = 1:4.
// Softmax in base-2: scores carry scale*log2(e); exp via exp2f (raw EX2).
// ---------------------------------------------------------------------------
#define AQ 128
#define AK 64

__global__ __launch_bounds__(128)
void attn_kernel()
{
    __shared__ float Ks[AK * HD_];
    __shared__ float Vs[AK * HD_];

    const int tid = threadIdx.x;
    const int q0  = blockIdx.x * AQ;
    const int bh  = blockIdx.y;          // b*H + h
    const int r   = q0 + tid;            // global q row within T
    const float scl2 = 0.125f * 1.4426950408889634f;  // scale * log2(e)

    float4 q4[16];
    {
        const float4* __restrict__ qg =
            (const float4*)&g_q[((size_t)bh * T_ + r) * HD_];
#pragma unroll
        for (int c = 0; c < 16; c++) q4[c] = qg[c];
    }
    float4 o4[16];
#pragma unroll
    for (int c = 0; c < 16; c++) o4[c] = make_float4(0.f, 0.f, 0.f, 0.f);
    float m = -1e30f, l = 0.f;

    const int nchunk = q0 / AK + 2;      // keys [0, q0+128)
    for (int ck = 0; ck < nchunk; ck++) {
        const int j0 = ck * AK;
        __syncthreads();                 // prev compute done before overwrite
        {
            const float4* __restrict__ kg =
                (const float4*)&g_k[((size_t)bh * T_ + j0) * HD_];
            const float4* __restrict__ vg =
                (const float4*)&g_v[((size_t)bh * T_ + j0) * HD_];
            float4* __restrict__ ks4 = (float4*)Ks;
            float4* __restrict__ vs4 = (float4*)Vs;
            float4 kr8[8], vr8[8];
#pragma unroll
            for (int it = 0; it < 8; it++) {
                kr8[it] = kg[tid + it * 128];
                vr8[it] = vg[tid + it * 128];
            }
#pragma unroll
            for (int it = 0; it < 8; it++) {
                ks4[tid + it * 128] = kr8[it];
                vs4[tid + it * 128] = vr8[it];
            }
        }
        __syncthreads();

        if (r < j0) continue;            // barrier counts still match
        const int rrel = r - j0;

#pragma unroll 1
        for (int js = 0; js < AK; js += 16) {
            if (js > rrel) break;
            float s[16];
#pragma unroll
            for (int jj = 0; jj < 16; jj++) {
                const float4* kr = (const float4*)&Ks[(js + jj) << 6];
                float ax = 0.f, ay = 0.f, az = 0.f, aw = 0.f;
#pragma unroll
                for (int c = 0; c < 16; c++) {
                    float4 kv = kr[c];
                    ax = fmaf(q4[c].x, kv.x, ax);
                    ay = fmaf(q4[c].y, kv.y, ay);
                    az = fmaf(q4[c].z, kv.z, az);
                    aw = fmaf(q4[c].w, kv.w, aw);
                }
                float sv = (ax + ay) + (az + aw);
                s[jj] = (js + jj > rrel) ? -1e30f : sv * scl2;
            }
            float mnew = m;
#pragma unroll
            for (int jj = 0; jj < 16; jj++) mnew = fmaxf(mnew, s[jj]);
            float corr = exp2f(m - mnew);
            m = mnew;
            l *= corr;
#pragma unroll
            for (int c = 0; c < 16; c++) {
                o4[c].x *= corr; o4[c].y *= corr;
                o4[c].z *= corr; o4[c].w *= corr;
            }
#pragma unroll
            for (int jj = 0; jj < 16; jj++) {
                float p = exp2f(s[jj] - mnew);
                l += p;
                const float4* vr = (const float4*)&Vs[(js + jj) << 6];
#pragma unroll
                for (int c = 0; c < 16; c++) {
                    float4 vv = vr[c];
                    o4[c].x = fmaf(p, vv.x, o4[c].x);
                    o4[c].y = fmaf(p, vv.y, o4[c].y);
                    o4[c].z = fmaf(p, vv.z, o4[c].z);
                    o4[c].w = fmaf(p, vv.w, o4[c].w);
                }
            }
        }
    }

    // write y[b, r, h*64 + :] = o / l
    const float inv = 1.0f / l;
    const int b = bh >> 4;
    const int h = bh & 15;
    float4* yout = (float4*)&g_y[((size_t)b * T_ + r) * D_ + h * HD_];
#pragma unroll
    for (int c = 0; c < 16; c++) {
        float4 w = o4[c];
        w.x *= inv; w.y *= inv; w.z *= inv; w.w *= inv;
        yout[c] = w;
    }
}

// ---------------------------------------------------------------------------
extern "C" void kernel_launch(void* const* d_in, const int* in_sizes, int n_in,
                              void* d_out, int out_size)
{
    const float* x    = (const float*)d_in[0];
    const float* Wqkv = (const float*)d_in[1];
    const float* bqkv = (const float*)d_in[2];
    const float* Wout = (const float*)d_in[3];
    const float* bout = (const float*)d_in[4];
    float* out = (float*)d_out;

    // 1) QKV projection + bias + scatter to [B,H,T,HD]
    sgemm_kernel<<<dim3(D3 / BN, NTOK / BM), 256>>>(
        x, Wqkv, bqkv, nullptr, NTOK, D3, D_, 1);

    // 2) causal flash attention -> g_y [B,T,D]
    attn_kernel<<<dim3(T_ / AQ, B_ * H_), 128>>>();

    // 3) output projection + bias
    sgemm_kernel<<<dim3(D_ / BN, NTOK / BM), 256>>>(
        nullptr, Wout, bout, out, NTOK, D_, D_, 2);
}